// round 1
// baseline (speedup 1.0000x reference)
#include <cuda_runtime.h>
#include <math.h>

// Problem constants
// B=4, L=256, Eq=Ek=2, D=512, H=8, dk=dv=64, KG=16
// inputs: 0 q[4,256,2,512] 1 k 2 v 3 mask[4,256,256]i32 4 gr_mask[4,16,256,256]
// 5 adj[4,256,256] 6 Wq[2,512,512] 7 Wk 8 Wv 9 Wq2 10 Wk2 11 Wv2(unused) 12 Wfc
// 13 grW1[2,2,8,16,16] 14 grb1[2,2,8,16] 15 grW2[2,2,8,16] 16 grb2[2,2,8]
// 17 ln_g[512] 18 ln_b[512]   output float [4,256,2,512]

__device__ float g_qp  [4*256*2*512];
__device__ float g_qp2 [4*256*2*512];
__device__ float g_kpT1[4*8*64*512];   // [b][h][d][pair], pair = k*2+j
__device__ float g_kpT2[4*8*64*512];
__device__ float g_vp  [4*256*2*512];  // [b][k][j][h*64+d]
__device__ float g_lsg [4*256*32*256]; // [b][q][c][k], c=(i*2+j)*8+h
__device__ float g_pre [4*256*2*512];
__device__ float g_res [4*256*2*512];

// ---------------- projection GEMMs: 5 projections x 2 ensembles ----------------
// C[m,f] = sum_d A[(m*2+ie)*512+d] * W[ie][d*512+f],  M=1024, N=512, K=512
__global__ __launch_bounds__(256) void proj_gemm_kernel(
    const float* __restrict__ qin, const float* __restrict__ kin,
    const float* __restrict__ vin,
    const float* __restrict__ Wq, const float* __restrict__ Wq2,
    const float* __restrict__ Wk, const float* __restrict__ Wk2,
    const float* __restrict__ Wv)
{
    __shared__ float As[64][17];
    __shared__ __align__(16) float Ws[16][64];

    int z = blockIdx.z;
    int proj = z >> 1;
    int ie = z & 1;
    const float* A;
    const float* W;
    if (proj == 0)      { A = qin; W = Wq;  }
    else if (proj == 1) { A = qin; W = Wq2; }
    else if (proj == 2) { A = kin; W = Wk;  }
    else if (proj == 3) { A = kin; W = Wk2; }
    else                { A = vin; W = Wv;  }
    W += ie * 512 * 512;

    int m0 = blockIdx.x * 64;
    int f0 = blockIdx.y * 64;
    int t = threadIdx.x;
    int tx = t & 15, ty = t >> 4;
    int lrow = t >> 2, lq = (t & 3) * 4;       // A tile loader
    int wrow = t >> 4, wcol = (t & 15) * 4;    // W tile loader

    float acc[4][4] = {};

    const float* Arow = A + ((size_t)(m0 + lrow) * 2 + ie) * 512 + lq;
    const float* Wrow = W + (size_t)wrow * 512 + f0 + wcol;

    for (int kt = 0; kt < 512; kt += 16) {
        float4 av = *(const float4*)(Arow + kt);
        As[lrow][lq + 0] = av.x; As[lrow][lq + 1] = av.y;
        As[lrow][lq + 2] = av.z; As[lrow][lq + 3] = av.w;
        *(float4*)&Ws[wrow][wcol] = *(const float4*)(Wrow + (size_t)kt * 512);
        __syncthreads();
#pragma unroll
        for (int kk = 0; kk < 16; kk++) {
            float a0 = As[ty * 4 + 0][kk];
            float a1 = As[ty * 4 + 1][kk];
            float a2 = As[ty * 4 + 2][kk];
            float a3 = As[ty * 4 + 3][kk];
            float4 bv = *(const float4*)&Ws[kk][tx * 4];
            acc[0][0] += a0 * bv.x; acc[0][1] += a0 * bv.y; acc[0][2] += a0 * bv.z; acc[0][3] += a0 * bv.w;
            acc[1][0] += a1 * bv.x; acc[1][1] += a1 * bv.y; acc[1][2] += a1 * bv.z; acc[1][3] += a1 * bv.w;
            acc[2][0] += a2 * bv.x; acc[2][1] += a2 * bv.y; acc[2][2] += a2 * bv.z; acc[2][3] += a2 * bv.w;
            acc[3][0] += a3 * bv.x; acc[3][1] += a3 * bv.y; acc[3][2] += a3 * bv.z; acc[3][3] += a3 * bv.w;
        }
        __syncthreads();
    }

    if (proj == 2 || proj == 3) {
        float* dst = (proj == 2) ? g_kpT1 : g_kpT2;
#pragma unroll
        for (int r = 0; r < 4; r++) {
            int m = m0 + ty * 4 + r;
            int bb = m >> 8, ll = m & 255;
#pragma unroll
            for (int c = 0; c < 4; c++) {
                int f = f0 + tx * 4 + c;
                int hh = f >> 6, dd = f & 63;
                dst[(((size_t)(bb * 8 + hh) * 64 + dd) * 512) + ll * 2 + ie] = acc[r][c];
            }
        }
    } else {
        float* dst = (proj == 0) ? g_qp : (proj == 1) ? g_qp2 : g_vp;
#pragma unroll
        for (int r = 0; r < 4; r++) {
            int m = m0 + ty * 4 + r;
            float4 st;
            st.x = acc[r][0]; st.y = acc[r][1]; st.z = acc[r][2]; st.w = acc[r][3];
            *(float4*)(dst + ((size_t)m * 2 + ie) * 512 + f0 + tx * 4) = st;
        }
    }
}

// ---------------- gate MLP: lsg[b][q][c][k] ----------------
__device__ __forceinline__ float log_sigmoid(float a) {
    return fminf(a, 0.f) - log1pf(__expf(-fabsf(a)));
}

__global__ __launch_bounds__(128) void gate_kernel(
    const float* __restrict__ gr_mask,
    const float* __restrict__ grW1, const float* __restrict__ grb1,
    const float* __restrict__ grW2, const float* __restrict__ grb2)
{
    __shared__ float W1s[8192];   // [c][g][m]
    __shared__ float b1s[512];    // [c][m]
    __shared__ float W2s[512];    // [c][m]
    __shared__ float b2s[32];     // [c]

    int t = threadIdx.x;
    for (int idx = t; idx < 8192; idx += 128) W1s[idx] = grW1[idx];
    for (int idx = t; idx < 512; idx += 128) { b1s[idx] = grb1[idx]; W2s[idx] = grW2[idx]; }
    if (t < 32) b2s[t] = grb2[t];

    int bq = blockIdx.x;            // b*256+q
    int b = bq >> 8, q = bq & 255;

    float xa[16], xb[16];
    const float* gm = gr_mask + (size_t)b * 16 * 65536 + (size_t)q * 256;
#pragma unroll
    for (int g = 0; g < 16; g++) {
        xa[g] = gm[(size_t)g * 65536 + t];
        xb[g] = gm[(size_t)g * 65536 + t + 128];
    }
    __syncthreads();

    float* outb = g_lsg + (size_t)bq * 32 * 256;
    for (int c = 0; c < 32; c++) {
        const float* w1c = &W1s[c * 256];
        float accA = 0.f, accB = 0.f;
#pragma unroll
        for (int m = 0; m < 16; m++) {
            float tA = b1s[c * 16 + m];
            float tB = tA;
#pragma unroll
            for (int g = 0; g < 16; g++) {
                float w = w1c[g * 16 + m];
                tA += xa[g] * w;
                tB += xb[g] * w;
            }
            float w2 = W2s[c * 16 + m];
            accA += fmaxf(tA, 0.f) * w2;
            accB += fmaxf(tB, 0.f) * w2;
        }
        float bias = b2s[c];
        outb[c * 256 + t]       = log_sigmoid(accA + bias);
        outb[c * 256 + t + 128] = log_sigmoid(accB + bias);
    }
}

// ---------------- fused attention: scores + softmax + PV ----------------
// block = (b, ie, h, q-tile of 4), 256 threads
__global__ __launch_bounds__(256) void attn_kernel(
    const float* __restrict__ adj, const int* __restrict__ mask)
{
    __shared__ float sq1[4][64];
    __shared__ float sq2[4][64];
    __shared__ float ss[4][512];
    __shared__ float red[8];
    __shared__ float smax[4], ssum[4];
    __shared__ float spv[4][4][64];  // [quarter][qq][d]

    int bx = blockIdx.x;
    int qt = bx & 63;
    int h  = (bx >> 6) & 7;
    int ie = (bx >> 9) & 1;
    int b  = bx >> 10;
    int q0 = qt * 4;

    int t = threadIdx.x;
    {
        int qq = t >> 6, d = t & 63;
        size_t off = ((size_t)(b * 256 + q0 + qq) * 2 + ie) * 512 + h * 64 + d;
        sq1[qq][d] = g_qp[off];
        sq2[qq][d] = g_qp2[off];
    }
    __syncthreads();

    // score phase: 2 pairs per thread
#pragma unroll
    for (int pi = 0; pi < 2; pi++) {
        int p = t + pi * 256;
        float a1[4] = {0.f, 0.f, 0.f, 0.f};
        float a2[4] = {0.f, 0.f, 0.f, 0.f};
        const float* k1p = g_kpT1 + (size_t)(b * 8 + h) * 64 * 512 + p;
        const float* k2p = g_kpT2 + (size_t)(b * 8 + h) * 64 * 512 + p;
#pragma unroll 16
        for (int d = 0; d < 64; d++) {
            float kv1 = k1p[(size_t)d * 512];
            float kv2 = k2p[(size_t)d * 512];
#pragma unroll
            for (int qq = 0; qq < 4; qq++) {
                a1[qq] += sq1[qq][d] * kv1;
                a2[qq] += sq2[qq][d] * kv2;
            }
        }
        int kk = p >> 1, j = p & 1;
        int c = (ie * 2 + j) * 8 + h;
#pragma unroll
        for (int qq = 0; qq < 4; qq++) {
            int qi = q0 + qq;
            int mrow = b * 65536 + qi * 256 + kk;
            float s;
            if (mask[mrow] == 0) {
                s = -1e9f;
            } else {
                float at = (kk <= qi) ? adj[mrow] : 0.f;
                float lsg = g_lsg[((size_t)(b * 256 + qi) * 32 + c) * 256 + kk];
                s = (a1[qq] * at + a2[qq] * (1.f - at)) * 0.125f + lsg;
            }
            ss[qq][p] = s;
        }
    }
    __syncthreads();

    int lane = t & 31, warp = t >> 5;
    // softmax per q-row (joint over 512 = Lk*Ek)
    for (int qq = 0; qq < 4; qq++) {
        float lv = fmaxf(ss[qq][t], ss[qq][t + 256]);
#pragma unroll
        for (int o = 16; o > 0; o >>= 1) lv = fmaxf(lv, __shfl_xor_sync(0xffffffffu, lv, o));
        if (lane == 0) red[warp] = lv;
        __syncthreads();
        if (t == 0) {
            float mm = red[0];
#pragma unroll
            for (int w = 1; w < 8; w++) mm = fmaxf(mm, red[w]);
            smax[qq] = mm;
        }
        __syncthreads();
        float mx = smax[qq];
        float e0 = __expf(ss[qq][t] - mx);
        float e1 = __expf(ss[qq][t + 256] - mx);
        ss[qq][t] = e0;
        ss[qq][t + 256] = e1;
        float lsum = e0 + e1;
#pragma unroll
        for (int o = 16; o > 0; o >>= 1) lsum += __shfl_xor_sync(0xffffffffu, lsum, o);
        if (lane == 0) red[warp] = lsum;
        __syncthreads();
        if (t == 0) {
            float sm = 0.f;
#pragma unroll
            for (int w = 0; w < 8; w++) sm += red[w];
            ssum[qq] = sm;
        }
        __syncthreads();
    }

    // PV phase
    {
        int quarter = t >> 6, d = t & 63;
        float acc[4] = {0.f, 0.f, 0.f, 0.f};
        int pbase = quarter * 128;
#pragma unroll 8
        for (int pp = 0; pp < 128; pp++) {
            int p = pbase + pp;
            int kk = p >> 1, j = p & 1;
            float v = g_vp[((size_t)(b * 256 + kk) * 2 + j) * 512 + h * 64 + d];
#pragma unroll
            for (int qq = 0; qq < 4; qq++) acc[qq] += ss[qq][p] * v;
        }
#pragma unroll
        for (int qq = 0; qq < 4; qq++) spv[quarter][qq][d] = acc[qq];
    }
    __syncthreads();
    if (t < 64) {
        int d = t;
#pragma unroll
        for (int qq = 0; qq < 4; qq++) {
            float o = (spv[0][qq][d] + spv[1][qq][d] + spv[2][qq][d] + spv[3][qq][d]) / ssum[qq];
            g_pre[((size_t)(b * 256 + q0 + qq) * 2 + ie) * 512 + h * 64 + d] = o;
        }
    }
}

// ---------------- fc GEMM + residual ----------------
__global__ __launch_bounds__(256) void fc_gemm_kernel(
    const float* __restrict__ Wfc, const float* __restrict__ qin)
{
    __shared__ float As[64][17];
    __shared__ __align__(16) float Ws[16][64];

    int ie = blockIdx.z;
    const float* A = g_pre;
    const float* W = Wfc + (size_t)ie * 512 * 512;

    int m0 = blockIdx.x * 64;
    int f0 = blockIdx.y * 64;
    int t = threadIdx.x;
    int tx = t & 15, ty = t >> 4;
    int lrow = t >> 2, lq = (t & 3) * 4;
    int wrow = t >> 4, wcol = (t & 15) * 4;

    float acc[4][4] = {};
    const float* Arow = A + ((size_t)(m0 + lrow) * 2 + ie) * 512 + lq;
    const float* Wrow = W + (size_t)wrow * 512 + f0 + wcol;

    for (int kt = 0; kt < 512; kt += 16) {
        float4 av = *(const float4*)(Arow + kt);
        As[lrow][lq + 0] = av.x; As[lrow][lq + 1] = av.y;
        As[lrow][lq + 2] = av.z; As[lrow][lq + 3] = av.w;
        *(float4*)&Ws[wrow][wcol] = *(const float4*)(Wrow + (size_t)kt * 512);
        __syncthreads();
#pragma unroll
        for (int kk = 0; kk < 16; kk++) {
            float a0 = As[ty * 4 + 0][kk];
            float a1 = As[ty * 4 + 1][kk];
            float a2 = As[ty * 4 + 2][kk];
            float a3 = As[ty * 4 + 3][kk];
            float4 bv = *(const float4*)&Ws[kk][tx * 4];
            acc[0][0] += a0 * bv.x; acc[0][1] += a0 * bv.y; acc[0][2] += a0 * bv.z; acc[0][3] += a0 * bv.w;
            acc[1][0] += a1 * bv.x; acc[1][1] += a1 * bv.y; acc[1][2] += a1 * bv.z; acc[1][3] += a1 * bv.w;
            acc[2][0] += a2 * bv.x; acc[2][1] += a2 * bv.y; acc[2][2] += a2 * bv.z; acc[2][3] += a2 * bv.w;
            acc[3][0] += a3 * bv.x; acc[3][1] += a3 * bv.y; acc[3][2] += a3 * bv.z; acc[3][3] += a3 * bv.w;
        }
        __syncthreads();
    }

#pragma unroll
    for (int r = 0; r < 4; r++) {
        int m = m0 + ty * 4 + r;
        size_t off = ((size_t)m * 2 + ie) * 512 + f0 + tx * 4;
        float4 rv = *(const float4*)(qin + off);
        float4 st;
        st.x = acc[r][0] + rv.x; st.y = acc[r][1] + rv.y;
        st.z = acc[r][2] + rv.z; st.w = acc[r][3] + rv.w;
        *(float4*)(g_res + off) = st;
    }
}

// ---------------- layernorm ----------------
__global__ __launch_bounds__(128) void ln_kernel(
    const float* __restrict__ ln_g, const float* __restrict__ ln_b,
    float* __restrict__ out)
{
    __shared__ float rs[4], rq[4];
    __shared__ float s_mu, s_inv;
    int row = blockIdx.x;
    int t = threadIdx.x;
    const float4 v = ((const float4*)(g_res + (size_t)row * 512))[t];
    float sum = v.x + v.y + v.z + v.w;
    float sq  = v.x * v.x + v.y * v.y + v.z * v.z + v.w * v.w;
#pragma unroll
    for (int o = 16; o > 0; o >>= 1) {
        sum += __shfl_xor_sync(0xffffffffu, sum, o);
        sq  += __shfl_xor_sync(0xffffffffu, sq, o);
    }
    int lane = t & 31, warp = t >> 5;
    if (lane == 0) { rs[warp] = sum; rq[warp] = sq; }
    __syncthreads();
    if (t == 0) {
        float S = rs[0] + rs[1] + rs[2] + rs[3];
        float Q = rq[0] + rq[1] + rq[2] + rq[3];
        float mu = S * (1.f / 512.f);
        float var = Q * (1.f / 512.f) - mu * mu;
        s_mu = mu;
        s_inv = rsqrtf(var + 1e-6f);
    }
    __syncthreads();
    float mu = s_mu, inv = s_inv;
    float4 g4 = ((const float4*)ln_g)[t];
    float4 b4 = ((const float4*)ln_b)[t];
    float4 y;
    y.x = (v.x - mu) * inv * g4.x + b4.x;
    y.y = (v.y - mu) * inv * g4.y + b4.y;
    y.z = (v.z - mu) * inv * g4.z + b4.z;
    y.w = (v.w - mu) * inv * g4.w + b4.w;
    ((float4*)(out + (size_t)row * 512))[t] = y;
}

extern "C" void kernel_launch(void* const* d_in, const int* in_sizes, int n_in,
                              void* d_out, int out_size) {
    const float* q       = (const float*)d_in[0];
    const float* k       = (const float*)d_in[1];
    const float* v       = (const float*)d_in[2];
    const int*   mask    = (const int*)d_in[3];
    const float* gr_mask = (const float*)d_in[4];
    const float* adj     = (const float*)d_in[5];
    const float* Wq      = (const float*)d_in[6];
    const float* Wk      = (const float*)d_in[7];
    const float* Wv      = (const float*)d_in[8];
    const float* Wq2     = (const float*)d_in[9];
    const float* Wk2     = (const float*)d_in[10];
    const float* Wfc     = (const float*)d_in[12];
    const float* grW1    = (const float*)d_in[13];
    const float* grb1    = (const float*)d_in[14];
    const float* grW2    = (const float*)d_in[15];
    const float* grb2    = (const float*)d_in[16];
    const float* ln_g    = (const float*)d_in[17];
    const float* ln_b    = (const float*)d_in[18];
    float* out = (float*)d_out;

    proj_gemm_kernel<<<dim3(16, 8, 10), 256>>>(q, k, v, Wq, Wq2, Wk, Wk2, Wv);
    gate_kernel<<<1024, 128>>>(gr_mask, grW1, grb1, grW2, grb2);
    attn_kernel<<<4096, 256>>>(adj, mask);
    fc_gemm_kernel<<<dim3(16, 8, 2), 256>>>(Wfc, q);
    ln_kernel<<<2048, 128>>>(ln_g, ln_b, out);
}

// round 2
// speedup vs baseline: 1.0884x; 1.0884x over previous
#include <cuda_runtime.h>
#include <math.h>

// B=4, L=256, Eq=Ek=2, D=512, H=8, dk=dv=64, KG=16
// inputs: 0 q[4,256,2,512] 1 k 2 v 3 mask[4,256,256]i32 4 gr_mask[4,16,256,256]
// 5 adj[4,256,256] 6 Wq[2,512,512] 7 Wk 8 Wv 9 Wq2 10 Wk2 11 Wv2(unused) 12 Wfc
// 13 grW1[2,2,8,16,16] 14 grb1 15 grW2 16 grb2 17 ln_g 18 ln_b
// output float [4,256,2,512]

typedef unsigned long long ull;

__device__ __forceinline__ ull pk(float lo, float hi) {
    ull r; asm("mov.b64 %0,{%1,%2};" : "=l"(r) : "f"(lo), "f"(hi)); return r;
}
__device__ __forceinline__ void fma2(ull& d, ull a, ull b) {
    asm("fma.rn.f32x2 %0,%1,%2,%0;" : "+l"(d) : "l"(a), "l"(b));
}
__device__ __forceinline__ void unpk(float& lo, float& hi, ull a) {
    asm("mov.b64 {%0,%1},%2;" : "=f"(lo), "=f"(hi) : "l"(a));
}

__device__ float g_qp [4*256*2*512];
__device__ float g_qp2[4*256*2*512];
__device__ float g_kpT[4*8*64*512*2];  // [b][h][d][pair][set], pair=k*2+j
__device__ float g_vp [4*256*2*512];   // [b][k][j][h*64+d]
__device__ float g_lsg[4*256*32*256];  // [b][q][c][k], c=(i*2+j)*8+h
__device__ float g_pre[4*256*2*512];
__device__ float g_res[4*256*2*512];

// ---------------- projection GEMMs (FFMA2, 128x128x8, double-buffered) ----------------
__global__ __launch_bounds__(256, 2) void proj_gemm_kernel(
    const float* __restrict__ qin, const float* __restrict__ kin,
    const float* __restrict__ vin,
    const float* __restrict__ Wq, const float* __restrict__ Wq2,
    const float* __restrict__ Wk, const float* __restrict__ Wk2,
    const float* __restrict__ Wv)
{
    __shared__ __align__(16) float As[2][8][132];
    __shared__ __align__(16) float Bs[2][8][128];

    int z = blockIdx.z;
    int proj = z >> 1;
    int ie = z & 1;
    const float* A;
    const float* W;
    if (proj == 0)      { A = qin; W = Wq;  }
    else if (proj == 1) { A = qin; W = Wq2; }
    else if (proj == 2) { A = kin; W = Wk;  }
    else if (proj == 3) { A = kin; W = Wk2; }
    else                { A = vin; W = Wv;  }
    W += (size_t)ie * 512 * 512;
    A += ie * 512;

    int m0 = blockIdx.x * 128;
    int f0 = blockIdx.y * 128;
    int t = threadIdx.x;
    int tx = t & 15, ty = t >> 4;
    int tm0 = ty * 8, tn0 = tx * 8;
    int ar = t >> 1, ac = (t & 1) * 4;
    int br = t >> 5, bc = (t & 31) * 4;

    ull acc[8][4];
#pragma unroll
    for (int r = 0; r < 8; r++)
#pragma unroll
        for (int c = 0; c < 4; c++) acc[r][c] = 0ull;

    const float* Aptr = A + (size_t)(m0 + ar) * 1024 + ac;
    const float* Bptr = W + (size_t)br * 512 + f0 + bc;

    {
        float4 av = *(const float4*)(Aptr);
        float4 bv = *(const float4*)(Bptr);
        As[0][ac + 0][ar] = av.x; As[0][ac + 1][ar] = av.y;
        As[0][ac + 2][ar] = av.z; As[0][ac + 3][ar] = av.w;
        *(float4*)&Bs[0][br][bc] = bv;
    }
    __syncthreads();

    int cur = 0;
    for (int kt = 8; kt <= 512; kt += 8) {
        float4 av2, bv2;
        bool has = kt < 512;
        if (has) {
            av2 = *(const float4*)(Aptr + kt);
            bv2 = *(const float4*)(Bptr + (size_t)kt * 512);
        }
#pragma unroll
        for (int kk = 0; kk < 8; kk++) {
            float4 a0 = *(const float4*)&As[cur][kk][tm0];
            float4 a1 = *(const float4*)&As[cur][kk][tm0 + 4];
            float4 b0 = *(const float4*)&Bs[cur][kk][tn0];
            float4 b1 = *(const float4*)&Bs[cur][kk][tn0 + 4];
            ull bp0 = pk(b0.x, b0.y), bp1 = pk(b0.z, b0.w);
            ull bp2 = pk(b1.x, b1.y), bp3 = pk(b1.z, b1.w);
            float am[8] = {a0.x, a0.y, a0.z, a0.w, a1.x, a1.y, a1.z, a1.w};
#pragma unroll
            for (int r = 0; r < 8; r++) {
                ull ad = pk(am[r], am[r]);
                fma2(acc[r][0], ad, bp0);
                fma2(acc[r][1], ad, bp1);
                fma2(acc[r][2], ad, bp2);
                fma2(acc[r][3], ad, bp3);
            }
        }
        if (has) {
            As[cur ^ 1][ac + 0][ar] = av2.x; As[cur ^ 1][ac + 1][ar] = av2.y;
            As[cur ^ 1][ac + 2][ar] = av2.z; As[cur ^ 1][ac + 3][ar] = av2.w;
            *(float4*)&Bs[cur ^ 1][br][bc] = bv2;
            __syncthreads();
            cur ^= 1;
        }
    }

    if (proj == 2 || proj == 3) {
        int set = proj - 2;
#pragma unroll
        for (int r = 0; r < 8; r++) {
            int m = m0 + tm0 + r;
            int bb = m >> 8, ll = m & 255;
#pragma unroll
            for (int c = 0; c < 4; c++) {
                float lo, hi;
                unpk(lo, hi, acc[r][c]);
                int f = f0 + tn0 + c * 2;
                int hh = f >> 6, dd = f & 63;
                size_t base = ((size_t)((bb * 8 + hh) * 64 + dd)) * 1024 + (ll * 2 + ie) * 2 + set;
                g_kpT[base] = lo;
                g_kpT[base + 1024] = hi;  // dd+1
            }
        }
    } else {
        float* dst = (proj == 0) ? g_qp : (proj == 1) ? g_qp2 : g_vp;
#pragma unroll
        for (int r = 0; r < 8; r++) {
            int m = m0 + tm0 + r;
            float lo0, hi0, lo1, hi1;
            float4 s;
            unpk(lo0, hi0, acc[r][0]); unpk(lo1, hi1, acc[r][1]);
            s.x = lo0; s.y = hi0; s.z = lo1; s.w = hi1;
            *(float4*)(dst + ((size_t)m * 2 + ie) * 512 + f0 + tn0) = s;
            unpk(lo0, hi0, acc[r][2]); unpk(lo1, hi1, acc[r][3]);
            s.x = lo0; s.y = hi0; s.z = lo1; s.w = hi1;
            *(float4*)(dst + ((size_t)m * 2 + ie) * 512 + f0 + tn0 + 4) = s;
        }
    }
}

// ---------------- gate MLP ----------------
__device__ __forceinline__ float lsgf(float a) {
    return fminf(a, 0.f) - __logf(1.f + __expf(-fabsf(a)));
}

__global__ __launch_bounds__(128) void gate_kernel(
    const float* __restrict__ gr_mask,
    const float* __restrict__ grW1, const float* __restrict__ grb1,
    const float* __restrict__ grW2, const float* __restrict__ grb2)
{
    __shared__ __align__(16) float W1t[8192];  // [c][m][g]
    __shared__ float b1s[512];
    __shared__ float W2s[512];
    __shared__ float b2s[32];

    int t = threadIdx.x;
    for (int idx = t; idx < 8192; idx += 128) {
        int c = idx >> 8, m = (idx >> 4) & 15, g = idx & 15;
        W1t[(c * 16 + m) * 16 + g] = grW1[(c * 16 + g) * 16 + m];
    }
    for (int idx = t; idx < 512; idx += 128) { b1s[idx] = grb1[idx]; W2s[idx] = grW2[idx]; }
    if (t < 32) b2s[t] = grb2[t];

    int blk = blockIdx.x;
    int b = blk >> 7;
    int q0 = (blk & 127) * 2;
    const float* gm0 = gr_mask + (size_t)b * 16 * 65536 + (size_t)q0 * 256;

    // xg[s][gp]: s: 0:(q0,t) 1:(q0,t+128) 2:(q0+1,t) 3:(q0+1,t+128)
    ull xg[4][8];
#pragma unroll
    for (int gp = 0; gp < 8; gp++) {
        size_t o0 = (size_t)(2 * gp) * 65536;
        size_t o1 = (size_t)(2 * gp + 1) * 65536;
        xg[0][gp] = pk(gm0[o0 + t],       gm0[o1 + t]);
        xg[1][gp] = pk(gm0[o0 + t + 128], gm0[o1 + t + 128]);
        xg[2][gp] = pk(gm0[o0 + 256 + t],       gm0[o1 + 256 + t]);
        xg[3][gp] = pk(gm0[o0 + 256 + t + 128], gm0[o1 + 256 + t + 128]);
    }
    __syncthreads();

    float* out0 = g_lsg + ((size_t)(b * 256 + q0)) * 8192;
    float* out1 = out0 + 8192;

    for (int c = 0; c < 32; c++) {
        float A0 = 0.f, A1 = 0.f, A2 = 0.f, A3 = 0.f;
#pragma unroll
        for (int m = 0; m < 16; m++) {
            const ull* wp = (const ull*)&W1t[(c * 16 + m) * 16];
            ull a0 = 0ull, a1 = 0ull, a2 = 0ull, a3 = 0ull;
#pragma unroll
            for (int gp = 0; gp < 8; gp++) {
                ull w = wp[gp];
                fma2(a0, xg[0][gp], w);
                fma2(a1, xg[1][gp], w);
                fma2(a2, xg[2][gp], w);
                fma2(a3, xg[3][gp], w);
            }
            float bias = b1s[c * 16 + m];
            float w2 = W2s[c * 16 + m];
            float lo, hi, h;
            unpk(lo, hi, a0); h = fmaxf(lo + hi + bias, 0.f); A0 = fmaf(h, w2, A0);
            unpk(lo, hi, a1); h = fmaxf(lo + hi + bias, 0.f); A1 = fmaf(h, w2, A1);
            unpk(lo, hi, a2); h = fmaxf(lo + hi + bias, 0.f); A2 = fmaf(h, w2, A2);
            unpk(lo, hi, a3); h = fmaxf(lo + hi + bias, 0.f); A3 = fmaf(h, w2, A3);
        }
        float b2 = b2s[c];
        out0[c * 256 + t]       = lsgf(A0 + b2);
        out0[c * 256 + t + 128] = lsgf(A1 + b2);
        out1[c * 256 + t]       = lsgf(A2 + b2);
        out1[c * 256 + t + 128] = lsgf(A3 + b2);
    }
}

// ---------------- fused attention: scores + softmax + PV (q-tile 16) ----------------
__global__ __launch_bounds__(256, 2) void attn_kernel(
    const float* __restrict__ adj, const int* __restrict__ mask)
{
    __shared__ __align__(16) float2 sqp[16][64];   // (qp, qp2), 8KB
    __shared__ __align__(16) float regB[8192];     // 32KB: ss2 / sspq / spv
    __shared__ float ssum[16];

    int bx = blockIdx.x;
    int qt = bx & 15;
    int h  = (bx >> 4) & 7;
    int ie = (bx >> 7) & 1;
    int b  = bx >> 8;
    int q0 = qt * 16;

    int t = threadIdx.x;

    for (int idx = t; idx < 1024; idx += 256) {
        int qq = idx >> 6, d = idx & 63;
        size_t off = ((size_t)(b * 256 + q0 + qq) * 2 + ie) * 512 + h * 64 + d;
        sqp[qq][d] = make_float2(g_qp[off], g_qp2[off]);
    }
    __syncthreads();

    // -------- score phase: thread t handles pairs p=2t, 2t+1 --------
    {
        ull acc0[16], acc1[16];
#pragma unroll
        for (int qq = 0; qq < 16; qq++) { acc0[qq] = 0ull; acc1[qq] = 0ull; }

        const float4* kptr = (const float4*)g_kpT + ((size_t)(b * 8 + h) * 64) * 256 + t;
#pragma unroll 4
        for (int d = 0; d < 64; d++) {
            float4 kv = kptr[(size_t)d * 256];
            ull kp0 = pk(kv.x, kv.y), kp1 = pk(kv.z, kv.w);
            const ull* qrow = (const ull*)&sqp[0][d];
#pragma unroll
            for (int qq = 0; qq < 16; qq++) {
                ull qd = qrow[qq * 64];
                fma2(acc0[qq], qd, kp0);
                fma2(acc1[qq], qd, kp1);
            }
        }

        // epilogue: combine sets, add gate, mask; kk = t
        float2* ss2 = (float2*)regB;
        int c0 = (ie * 2 + 0) * 8 + h;
        int c1 = (ie * 2 + 1) * 8 + h;
#pragma unroll
        for (int qq = 0; qq < 16; qq++) {
            int qi = q0 + qq;
            int mrow = b * 65536 + qi * 256 + t;
            int mv = mask[mrow];
            float at = (t <= qi) ? adj[mrow] : 0.f;
            float s1a, s2a, s1b, s2b;
            unpk(s1a, s2a, acc0[qq]);
            unpk(s1b, s2b, acc1[qq]);
            float sa, sb;
            if (mv == 0) {
                sa = -1e9f; sb = -1e9f;
            } else {
                size_t lbase = ((size_t)(b * 256 + qi) * 32) * 256 + t;
                float l0 = g_lsg[lbase + (size_t)c0 * 256];
                float l1 = g_lsg[lbase + (size_t)c1 * 256];
                sa = (s1a * at + s2a * (1.f - at)) * 0.125f + l0;
                sb = (s1b * at + s2b * (1.f - at)) * 0.125f + l1;
            }
            ss2[qq * 256 + t] = make_float2(sa, sb);
        }
    }
    __syncthreads();

    // -------- softmax: warp w handles rows 2w, 2w+1 --------
    {
        int lane = t & 31, w = t >> 5;
        float2* r0 = (float2*)regB + (2 * w) * 256;
        float2* r1 = r0 + 256;
        float2 v0[8], v1[8];
        float mx0 = -1e30f, mx1 = -1e30f;
#pragma unroll
        for (int i = 0; i < 8; i++) {
            v0[i] = r0[lane + 32 * i];
            v1[i] = r1[lane + 32 * i];
            mx0 = fmaxf(mx0, fmaxf(v0[i].x, v0[i].y));
            mx1 = fmaxf(mx1, fmaxf(v1[i].x, v1[i].y));
        }
#pragma unroll
        for (int o = 16; o > 0; o >>= 1) {
            mx0 = fmaxf(mx0, __shfl_xor_sync(0xffffffffu, mx0, o));
            mx1 = fmaxf(mx1, __shfl_xor_sync(0xffffffffu, mx1, o));
        }
        float s0 = 0.f, s1 = 0.f;
#pragma unroll
        for (int i = 0; i < 8; i++) {
            v0[i].x = __expf(v0[i].x - mx0); v0[i].y = __expf(v0[i].y - mx0);
            v1[i].x = __expf(v1[i].x - mx1); v1[i].y = __expf(v1[i].y - mx1);
            s0 += v0[i].x + v0[i].y;
            s1 += v1[i].x + v1[i].y;
        }
#pragma unroll
        for (int o = 16; o > 0; o >>= 1) {
            s0 += __shfl_xor_sync(0xffffffffu, s0, o);
            s1 += __shfl_xor_sync(0xffffffffu, s1, o);
        }
        if (lane == 0) { ssum[2 * w] = s0; ssum[2 * w + 1] = s1; }
        __syncwarp();
        // write q-pair-packed exp: sspq[w][p] = (e[2w][p], e[2w+1][p])
        float2* dst = (float2*)regB + w * 512;
#pragma unroll
        for (int i = 0; i < 8; i++) {
            int c = lane + 32 * i;
            dst[2 * c]     = make_float2(v0[i].x, v1[i].x);
            dst[2 * c + 1] = make_float2(v0[i].y, v1[i].y);
        }
    }
    __syncthreads();

    // -------- PV phase --------
    {
        int d = t & 63, grp = t >> 6;
        const float* vb = g_vp + ((size_t)b * 512) * 512 + h * 64 + d;
        ull o[8];
#pragma unroll
        for (int r = 0; r < 8; r++) o[r] = 0ull;
        const ull* sp = (const ull*)regB;
        int p0 = grp * 128;
#pragma unroll 4
        for (int pp = 0; pp < 128; pp++) {
            int p = p0 + pp;
            float v = __ldg(vb + (size_t)p * 512);
            ull vd = pk(v, v);
#pragma unroll
            for (int r = 0; r < 8; r++) fma2(o[r], sp[r * 512 + p], vd);
        }
        __syncthreads();
        if (grp) {
            float* spv = regB + (grp - 1) * 1024;
#pragma unroll
            for (int r = 0; r < 8; r++) {
                float lo, hi;
                unpk(lo, hi, o[r]);
                spv[(2 * r) * 64 + d] = lo;
                spv[(2 * r + 1) * 64 + d] = hi;
            }
        }
        __syncthreads();
        if (grp == 0) {
#pragma unroll
            for (int r = 0; r < 8; r++) {
                float lo, hi;
                unpk(lo, hi, o[r]);
                float sum0 = lo + regB[(2 * r) * 64 + d] + regB[1024 + (2 * r) * 64 + d] + regB[2048 + (2 * r) * 64 + d];
                float sum1 = hi + regB[(2 * r + 1) * 64 + d] + regB[1024 + (2 * r + 1) * 64 + d] + regB[2048 + (2 * r + 1) * 64 + d];
                int qq0 = 2 * r, qq1 = 2 * r + 1;
                g_pre[((size_t)(b * 256 + q0 + qq0) * 2 + ie) * 512 + h * 64 + d] = sum0 / ssum[qq0];
                g_pre[((size_t)(b * 256 + q0 + qq1) * 2 + ie) * 512 + h * 64 + d] = sum1 / ssum[qq1];
            }
        }
    }
}

// ---------------- fc GEMM + residual (FFMA2) ----------------
__global__ __launch_bounds__(256, 2) void fc_gemm_kernel(
    const float* __restrict__ Wfc, const float* __restrict__ qin)
{
    __shared__ __align__(16) float As[2][8][132];
    __shared__ __align__(16) float Bs[2][8][128];

    int ie = blockIdx.z;
    const float* A = g_pre + ie * 512;
    const float* W = Wfc + (size_t)ie * 512 * 512;

    int m0 = blockIdx.x * 128;
    int f0 = blockIdx.y * 128;
    int t = threadIdx.x;
    int tx = t & 15, ty = t >> 4;
    int tm0 = ty * 8, tn0 = tx * 8;
    int ar = t >> 1, ac = (t & 1) * 4;
    int br = t >> 5, bc = (t & 31) * 4;

    ull acc[8][4];
#pragma unroll
    for (int r = 0; r < 8; r++)
#pragma unroll
        for (int c = 0; c < 4; c++) acc[r][c] = 0ull;

    const float* Aptr = A + (size_t)(m0 + ar) * 1024 + ac;
    const float* Bptr = W + (size_t)br * 512 + f0 + bc;

    {
        float4 av = *(const float4*)(Aptr);
        float4 bv = *(const float4*)(Bptr);
        As[0][ac + 0][ar] = av.x; As[0][ac + 1][ar] = av.y;
        As[0][ac + 2][ar] = av.z; As[0][ac + 3][ar] = av.w;
        *(float4*)&Bs[0][br][bc] = bv;
    }
    __syncthreads();

    int cur = 0;
    for (int kt = 8; kt <= 512; kt += 8) {
        float4 av2, bv2;
        bool has = kt < 512;
        if (has) {
            av2 = *(const float4*)(Aptr + kt);
            bv2 = *(const float4*)(Bptr + (size_t)kt * 512);
        }
#pragma unroll
        for (int kk = 0; kk < 8; kk++) {
            float4 a0 = *(const float4*)&As[cur][kk][tm0];
            float4 a1 = *(const float4*)&As[cur][kk][tm0 + 4];
            float4 b0 = *(const float4*)&Bs[cur][kk][tn0];
            float4 b1 = *(const float4*)&Bs[cur][kk][tn0 + 4];
            ull bp0 = pk(b0.x, b0.y), bp1 = pk(b0.z, b0.w);
            ull bp2 = pk(b1.x, b1.y), bp3 = pk(b1.z, b1.w);
            float am[8] = {a0.x, a0.y, a0.z, a0.w, a1.x, a1.y, a1.z, a1.w};
#pragma unroll
            for (int r = 0; r < 8; r++) {
                ull ad = pk(am[r], am[r]);
                fma2(acc[r][0], ad, bp0);
                fma2(acc[r][1], ad, bp1);
                fma2(acc[r][2], ad, bp2);
                fma2(acc[r][3], ad, bp3);
            }
        }
        if (has) {
            As[cur ^ 1][ac + 0][ar] = av2.x; As[cur ^ 1][ac + 1][ar] = av2.y;
            As[cur ^ 1][ac + 2][ar] = av2.z; As[cur ^ 1][ac + 3][ar] = av2.w;
            *(float4*)&Bs[cur ^ 1][br][bc] = bv2;
            __syncthreads();
            cur ^= 1;
        }
    }

#pragma unroll
    for (int r = 0; r < 8; r++) {
        int m = m0 + tm0 + r;
        size_t off = ((size_t)m * 2 + ie) * 512 + f0 + tn0;
        float4 rv0 = *(const float4*)(qin + off);
        float4 rv1 = *(const float4*)(qin + off + 4);
        float lo0, hi0, lo1, hi1;
        float4 s;
        unpk(lo0, hi0, acc[r][0]); unpk(lo1, hi1, acc[r][1]);
        s.x = lo0 + rv0.x; s.y = hi0 + rv0.y; s.z = lo1 + rv0.z; s.w = hi1 + rv0.w;
        *(float4*)(g_res + off) = s;
        unpk(lo0, hi0, acc[r][2]); unpk(lo1, hi1, acc[r][3]);
        s.x = lo0 + rv1.x; s.y = hi0 + rv1.y; s.z = lo1 + rv1.z; s.w = hi1 + rv1.w;
        *(float4*)(g_res + off + 4) = s;
    }
}

// ---------------- layernorm ----------------
__global__ __launch_bounds__(128) void ln_kernel(
    const float* __restrict__ ln_g, const float* __restrict__ ln_b,
    float* __restrict__ out)
{
    __shared__ float rs[4], rq[4];
    __shared__ float s_mu, s_inv;
    int row = blockIdx.x;
    int t = threadIdx.x;
    const float4 v = ((const float4*)(g_res + (size_t)row * 512))[t];
    float sum = v.x + v.y + v.z + v.w;
    float sq  = v.x * v.x + v.y * v.y + v.z * v.z + v.w * v.w;
#pragma unroll
    for (int o = 16; o > 0; o >>= 1) {
        sum += __shfl_xor_sync(0xffffffffu, sum, o);
        sq  += __shfl_xor_sync(0xffffffffu, sq, o);
    }
    int lane = t & 31, warp = t >> 5;
    if (lane == 0) { rs[warp] = sum; rq[warp] = sq; }
    __syncthreads();
    if (t == 0) {
        float S = rs[0] + rs[1] + rs[2] + rs[3];
        float Q = rq[0] + rq[1] + rq[2] + rq[3];
        float mu = S * (1.f / 512.f);
        float var = Q * (1.f / 512.f) - mu * mu;
        s_mu = mu;
        s_inv = rsqrtf(var + 1e-6f);
    }
    __syncthreads();
    float mu = s_mu, inv = s_inv;
    float4 g4 = ((const float4*)ln_g)[t];
    float4 b4 = ((const float4*)ln_b)[t];
    float4 y;
    y.x = (v.x - mu) * inv * g4.x + b4.x;
    y.y = (v.y - mu) * inv * g4.y + b4.y;
    y.z = (v.z - mu) * inv * g4.z + b4.z;
    y.w = (v.w - mu) * inv * g4.w + b4.w;
    ((float4*)(out + (size_t)row * 512))[t] = y;
}

extern "C" void kernel_launch(void* const* d_in, const int* in_sizes, int n_in,
                              void* d_out, int out_size) {
    const float* q       = (const float*)d_in[0];
    const float* k       = (const float*)d_in[1];
    const float* v       = (const float*)d_in[2];
    const int*   mask    = (const int*)d_in[3];
    const float* gr_mask = (const float*)d_in[4];
    const float* adj     = (const float*)d_in[5];
    const float* Wq      = (const float*)d_in[6];
    const float* Wk      = (const float*)d_in[7];
    const float* Wv      = (const float*)d_in[8];
    const float* Wq2     = (const float*)d_in[9];
    const float* Wk2     = (const float*)d_in[10];
    const float* Wfc     = (const float*)d_in[12];
    const float* grW1    = (const float*)d_in[13];
    const float* grb1    = (const float*)d_in[14];
    const float* grW2    = (const float*)d_in[15];
    const float* grb2    = (const float*)d_in[16];
    const float* ln_g    = (const float*)d_in[17];
    const float* ln_b    = (const float*)d_in[18];
    float* out = (float*)d_out;

    proj_gemm_kernel<<<dim3(8, 4, 10), 256>>>(q, k, v, Wq, Wq2, Wk, Wk2, Wv);
    gate_kernel<<<512, 128>>>(gr_mask, grW1, grb1, grW2, grb2);
    attn_kernel<<<1024, 256>>>(adj, mask);
    fc_gemm_kernel<<<dim3(8, 4, 2), 256>>>(Wfc, q);
    ln_kernel<<<2048, 128>>>(ln_g, ln_b, out);
}